// round 7
// baseline (speedup 1.0000x reference)
#include <cuda_runtime.h>
#include <math.h>

#define D      512
#define KNN    20
#define MAXN   100000
#define MAXCH  128
#define CHUNK  1024
#define FINF   3.0e38f

// ---------------- persistent scratch ----------------
__device__ float g_tn2[MAXN];
__device__ float g_score[MAXN];
__device__ float g_sq[KNN * MAXN];
__device__ float g_cand_d[KNN * MAXCH * KNN];
__device__ int   g_cand_i[KNN * MAXCH * KNN];
__device__ float g_nb[KNN * D];
__device__ float g_pxk[KNN];
__device__ float g_sqnn[KNN * KNN];

// ---------------- f32x2 packed helpers ----------------
static __device__ __forceinline__ void fma2(unsigned long long& acc,
                                            unsigned long long a,
                                            unsigned long long b) {
    asm("fma.rn.f32x2 %0, %1, %2, %0;" : "+l"(acc) : "l"(a), "l"(b));
}
static __device__ __forceinline__ float2 u2f(unsigned long long u) {
    float2 f;
    asm("mov.b64 {%0, %1}, %2;" : "=f"(f.x), "=f"(f.y) : "l"(u));
    return f;
}

// ---------------- pass 1: tn2 and score = tn2 - 2*dot(X,t) ----------------
__global__ void k_pass1(const float* __restrict__ X, const float* __restrict__ T, int n) {
    int w    = blockIdx.x * (blockDim.x >> 5) + (threadIdx.x >> 5);
    int lane = threadIdx.x & 31;
    if (w >= n) return;
    const float4* row = (const float4*)(T + (size_t)w * D);
    const float4* xv  = (const float4*)X;
    float tn2 = 0.f, dx = 0.f;
#pragma unroll
    for (int i = 0; i < 4; i++) {
        float4 t = row[lane + 32 * i];
        float4 x = __ldg(&xv[lane + 32 * i]);
        tn2 += t.x * t.x + t.y * t.y + t.z * t.z + t.w * t.w;
        dx  += t.x * x.x + t.y * x.y + t.z * x.z + t.w * x.w;
    }
#pragma unroll
    for (int o = 16; o; o >>= 1) {
        tn2 += __shfl_xor_sync(0xffffffffu, tn2, o);
        dx  += __shfl_xor_sync(0xffffffffu, dx, o);
    }
    if (lane == 0) { g_tn2[w] = tn2; g_score[w] = tn2 - 2.f * dx; }
}

// ---------------- stage A: warp-per-chunk register top-20, no syncs ----------------
__global__ void k_topk_a(int src, int n, int nch) {
    int wg   = blockIdx.x * (blockDim.x >> 5) + (threadIdx.x >> 5);
    int lane = threadIdx.x & 31;
    int rows = src ? KNN : 1;
    if (wg >= rows * nch) return;
    int row = wg / nch, c = wg % nch;
    const float* v = src ? (g_sq + (size_t)row * n) : g_score;
    int base = c * CHUNK;

    float val[32];
#pragma unroll
    for (int r = 0; r < 32; r++) {
        int g = base + lane + 32 * r;
        val[r] = (g < n) ? v[g] : FINF;
    }
    float* od = g_cand_d + ((size_t)row * MAXCH + c) * KNN;
    int*   oi = g_cand_i + ((size_t)row * MAXCH + c) * KNN;
    int ibase = base + lane;

    for (int it = 0; it < KNN; it++) {
        float bv = val[0]; int br = 0;
#pragma unroll
        for (int r = 1; r < 32; r++)
            if (val[r] < bv) { bv = val[r]; br = r; }
        int bi = (bv >= FINF) ? 0x7fffffff : (ibase + (br << 5));
#pragma unroll
        for (int o = 16; o; o >>= 1) {
            float ov = __shfl_xor_sync(0xffffffffu, bv, o);
            int   oj = __shfl_xor_sync(0xffffffffu, bi, o);
            if (ov < bv || (ov == bv && oj < bi)) { bv = ov; bi = oj; }
        }
        int rel = bi - ibase;
#pragma unroll
        for (int r = 0; r < 32; r++)
            if (rel == (r << 5)) val[r] = FINF;
        if (lane == 0) { od[it] = bv; oi[it] = bi; }
    }
}

// ---------------- stage B: 2-phase warp-register merge, fused epilogues ----------------
__global__ void k_topk_b(int nchunks, int mode, const float* __restrict__ X,
                         const float* __restrict__ T, int n) {
    int row = blockIdx.x;
    int m = nchunks * KNN;
    int tid = threadIdx.x, lane = tid & 31, w = tid >> 5;
    __shared__ float s_cv[8 * KNN];
    __shared__ int   s_ci[8 * KNN];
    __shared__ int   s_fi[KNN];
    const float* cd = g_cand_d + (size_t)row * MAXCH * KNN;
    const int*   ci = g_cand_i + (size_t)row * MAXCH * KNN;

    float val[8]; int idx[8];
#pragma unroll
    for (int r = 0; r < 8; r++) {
        int j = w * 256 + lane + 32 * r;
        bool ok = j < m;
        val[r] = ok ? cd[j] : FINF;
        idx[r] = ok ? ci[j] : 0x7fffffff;
    }
    for (int it = 0; it < KNN; it++) {
        float bv = val[0]; int bi = idx[0];
#pragma unroll
        for (int r = 1; r < 8; r++)
            if (val[r] < bv || (val[r] == bv && idx[r] < bi)) { bv = val[r]; bi = idx[r]; }
#pragma unroll
        for (int o = 16; o; o >>= 1) {
            float ov = __shfl_xor_sync(0xffffffffu, bv, o);
            int   oj = __shfl_xor_sync(0xffffffffu, bi, o);
            if (ov < bv || (ov == bv && oj < bi)) { bv = ov; bi = oj; }
        }
#pragma unroll
        for (int r = 0; r < 8; r++)
            if (idx[r] == bi) val[r] = FINF;
        if (lane == 0) { s_cv[w * KNN + it] = bv; s_ci[w * KNN + it] = bi; }
    }
    __syncthreads();

    if (w == 0) {
        float v2[5]; int i2[5];
#pragma unroll
        for (int r = 0; r < 5; r++) { int j = lane + 32 * r; v2[r] = s_cv[j]; i2[r] = s_ci[j]; }
        for (int it = 0; it < KNN; it++) {
            float bv = v2[0]; int bi = i2[0];
#pragma unroll
            for (int r = 1; r < 5; r++)
                if (v2[r] < bv || (v2[r] == bv && i2[r] < bi)) { bv = v2[r]; bi = i2[r]; }
#pragma unroll
            for (int o = 16; o; o >>= 1) {
                float ov = __shfl_xor_sync(0xffffffffu, bv, o);
                int   oj = __shfl_xor_sync(0xffffffffu, bi, o);
                if (ov < bv || (ov == bv && oj < bi)) { bv = ov; bi = oj; }
            }
#pragma unroll
            for (int r = 0; r < 5; r++)
                if (i2[r] == bi) v2[r] = FINF;
            if (lane == 0) s_fi[it] = bi;
        }
    }
    __syncthreads();

    if (mode == 0) {
        for (int i = w; i < KNN; i += 8) {
            int rowi = s_fi[i];
            float px = 0.f;
#pragma unroll
            for (int q = 0; q < 4; q++) {
                float4 t = ((const float4*)(T + (size_t)rowi * D))[lane + 32 * q];
                float4 x = ((const float4*)X)[lane + 32 * q];
                ((float4*)g_nb)[i * (D / 4) + lane + 32 * q] = t;
                float a = t.x - x.x, b = t.y - x.y, cc = t.z - x.z, d = t.w - x.w;
                px += a * a + b * b + cc * cc + d * d;
            }
#pragma unroll
            for (int o = 16; o; o >>= 1) px += __shfl_xor_sync(0xffffffffu, px, o);
            if (lane == 0) g_pxk[i] = px;
        }
    } else {
        for (int j = w; j < KNN; j += 8) {
            int rowj = s_fi[j];
            float s = 0.f;
#pragma unroll
            for (int q = 0; q < 4; q++) {
                float4 t  = ((const float4*)(T + (size_t)rowj * D))[lane + 32 * q];
                float4 nb = ((const float4*)g_nb)[row * (D / 4) + lane + 32 * q];
                float a = t.x - nb.x, b = t.y - nb.y, cc = t.z - nb.z, d = t.w - nb.w;
                s += a * a + b * b + cc * cc + d * d;
            }
#pragma unroll
            for (int o = 16; o; o >>= 1) s += __shfl_xor_sync(0xffffffffu, s, o);
            if (lane == 0) g_sqnn[row * KNN + j] = s;
        }
    }
}

// ---------------- pass 2: per-warp pipeline, 1 point per lane, 782 blocks ----
#define P2T   128                 // threads/block (4 warps)
#define WPTS  32                  // points per warp (1 per lane)
#define P2P   128                 // points per block
#define DCF   16                  // floats per chunk per point
#define NCH2  (D / DCF)           // 32 chunks
#define ROWB  80                  // bytes per point row in a stage (64 + 16 pad)
#define TSTG  (WPTS * ROWB)       // 2560 B
#define NBST  (KNN * DCF * 4)     // 1280 B nb chunk
#define WSTG  (TSTG + NBST)       // 3840 B per stage
#define WBUF  (2 * WSTG)          // 7680 B per warp
#define SMEM2 (4 * WBUF)          // 30720 B per block

static __device__ __forceinline__ void cpa16(unsigned int dst, const float* src, int sz) {
    asm volatile("cp.async.cg.shared.global [%0], [%1], 16, %2;"
                 :: "r"(dst), "l"(src), "r"(sz));
}

// issue one chunk (t rows + nb chunk) into this warp's stage buffer; 1 commit group
static __device__ __forceinline__ void p2_issue(const float* __restrict__ T, int n,
                                                int wpbase, int lane,
                                                unsigned int tb, unsigned int nbb, int c) {
#pragma unroll
    for (int rr = 0; rr < 4; rr++) {
        int q  = lane + rr * 32;           // 128 granules = 32 pts x 4
        int pt = q >> 2, fc = q & 3;
        int gp = wpbase + pt;
        int sz = (gp < n) ? 16 : 0;
        const float* src = T + (size_t)(gp < n ? gp : 0) * D + c * DCF + fc * 4;
        cpa16(tb + pt * ROWB + fc * 16, src, sz);
    }
#pragma unroll
    for (int rr = 0; rr < 3; rr++) {       // 80 granules = 20 k x 4
        int g = lane + rr * 32;
        if (g < KNN * 4) {
            int k = g >> 2, piece = g & 3;
            cpa16(nbb + g * 16, g_nb + k * D + c * DCF + piece * 4, 16);
        }
    }
    asm volatile("cp.async.commit_group;");
}

__global__ __launch_bounds__(P2T, 6) void k_pass2(const float* __restrict__ T, int n) {
    extern __shared__ char sh[];
    int tid  = threadIdx.x;
    int lane = tid & 31, w = tid >> 5;
    int wpbase = blockIdx.x * P2P + w * WPTS;

    char* wbg = sh + w * WBUF;   // generic pointer to this warp's buffers
    unsigned int wb = (unsigned int)__cvta_generic_to_shared(wbg);
    unsigned int tb0 = wb,            nb0 = wb + TSTG;
    unsigned int tb1 = wb + WSTG,     nb1 = wb + WSTG + TSTG;

    p2_issue(T, n, wpbase, lane, tb0, nb0, 0);
    p2_issue(T, n, wpbase, lane, tb1, nb1, 1);

    unsigned long long a0[KNN];
#pragma unroll
    for (int k = 0; k < KNN; k++) a0[k] = 0ull;

#pragma unroll 1
    for (int c = 0; c < NCH2; c++) {
        if (c == NCH2 - 1) asm volatile("cp.async.wait_group 0;");
        else               asm volatile("cp.async.wait_group 1;");
        __syncwarp();

        const char* stage = wbg + (c & 1) * WSTG;
        const ulonglong2* t0p = (const ulonglong2*)(stage + lane * ROWB);
        const ulonglong2* nbp = (const ulonglong2*)(stage + TSTG);
#pragma unroll
        for (int dq = 0; dq < DCF / 4; dq++) {
            ulonglong2 t0 = t0p[dq];
#pragma unroll
            for (int k = 0; k < KNN; k++) {
                ulonglong2 nb = nbp[k * 4 + dq];
                fma2(a0[k], t0.x, nb.x);
                fma2(a0[k], t0.y, nb.y);
            }
        }
        __syncwarp();
        if (c + 2 < NCH2) {
            unsigned int tb = (c & 1) ? tb1 : tb0;
            unsigned int nbb = (c & 1) ? nb1 : nb0;
            p2_issue(T, n, wpbase, lane, tb, nbb, c + 2);
        }
    }

    int g0 = wpbase + lane;
    if (g0 < n) {
        float tn0 = g_tn2[g0];
#pragma unroll
        for (int k = 0; k < KNN; k++) {
            float2 f0 = u2f(a0[k]);
            g_sq[(size_t)k * n + g0] = tn0 - 2.f * (f0.x + f0.y);
        }
    }
}

// ---------------- final scalar ----------------
__global__ void k_final(float* out) {
    int lane = threadIdx.x;
    float norm = 0.f, px = 0.f;
    if (lane < KNN) {
        float s = 0.f;
#pragma unroll
        for (int j = 0; j < KNN; j++) s += g_sqnn[lane * KNN + j];
        norm = sqrtf(s / (float)KNN);
        px = g_pxk[lane];
    }
#pragma unroll
    for (int o = 16; o; o >>= 1) {
        norm += __shfl_xor_sync(0xffffffffu, norm, o);
        px   += __shfl_xor_sync(0xffffffffu, px, o);
    }
    if (lane == 0) {
        float pdx = sqrtf(px / (float)KNN);
        float lof = pdx / norm * (float)KNN - 1.f;
        float r = erff(lof * 0.7071067811865476f);
        out[0] = fmaxf(r, 0.f);
    }
}

// ---------------- launch ----------------
extern "C" void kernel_launch(void* const* d_in, const int* in_sizes, int n_in,
                              void* d_out, int out_size) {
    const float* A = (const float*)d_in[0];
    const float* B = (const float*)d_in[1];
    const float *X, *T;
    int n;
    if (in_sizes[0] == D) { X = A; T = B; n = in_sizes[1] / D; }
    else                  { X = B; T = A; n = in_sizes[0] / D; }
    if (n > MAXN) n = MAXN;

    int nch = (n + CHUNK - 1) / CHUNK;

    cudaFuncSetAttribute(k_pass2, cudaFuncAttributeMaxDynamicSharedMemorySize, SMEM2);

    k_pass1<<<(n + 7) / 8, 256>>>(X, T, n);
    k_topk_a<<<(nch + 7) / 8, 256>>>(0, n, nch);
    k_topk_b<<<1, 256>>>(nch, 0, X, T, n);
    k_pass2<<<(n + P2P - 1) / P2P, P2T, SMEM2>>>(T, n);
    k_topk_a<<<(nch * KNN + 7) / 8, 256>>>(1, n, nch);
    k_topk_b<<<KNN, 256>>>(nch, 1, X, T, n);
    k_final<<<1, 32>>>((float*)d_out);
}

// round 8
// speedup vs baseline: 1.0788x; 1.0788x over previous
#include <cuda_runtime.h>
#include <math.h>

#define D      512
#define KNN    20
#define MAXN   100000
#define MAXCH  128
#define CHUNK  1024
#define FINF   3.0e38f

// ---------------- persistent scratch ----------------
__device__ float g_tn2[MAXN];
__device__ float g_score[MAXN];
__device__ float g_sq[KNN * MAXN];
__device__ float g_cand_d[KNN * MAXCH * KNN];
__device__ int   g_cand_i[KNN * MAXCH * KNN];
__device__ float g_nb[KNN * D];
__device__ float g_pxk[KNN];
__device__ float g_sqnn[KNN * KNN];

// ---------------- f32x2 packed helpers ----------------
static __device__ __forceinline__ void fma2(unsigned long long& acc,
                                            unsigned long long a,
                                            unsigned long long b) {
    asm("fma.rn.f32x2 %0, %1, %2, %0;" : "+l"(acc) : "l"(a), "l"(b));
}
static __device__ __forceinline__ float2 u2f(unsigned long long u) {
    float2 f;
    asm("mov.b64 {%0, %1}, %2;" : "=f"(f.x), "=f"(f.y) : "l"(u));
    return f;
}

// ---------------- pass 1: tn2 and score = tn2 - 2*dot(X,t) ----------------
__global__ void k_pass1(const float* __restrict__ X, const float* __restrict__ T, int n) {
    int w    = blockIdx.x * (blockDim.x >> 5) + (threadIdx.x >> 5);
    int lane = threadIdx.x & 31;
    if (w >= n) return;
    const float4* row = (const float4*)(T + (size_t)w * D);
    const float4* xv  = (const float4*)X;
    float tn2 = 0.f, dx = 0.f;
#pragma unroll
    for (int i = 0; i < 4; i++) {
        float4 t = row[lane + 32 * i];
        float4 x = __ldg(&xv[lane + 32 * i]);
        tn2 += t.x * t.x + t.y * t.y + t.z * t.z + t.w * t.w;
        dx  += t.x * x.x + t.y * x.y + t.z * x.z + t.w * x.w;
    }
#pragma unroll
    for (int o = 16; o; o >>= 1) {
        tn2 += __shfl_xor_sync(0xffffffffu, tn2, o);
        dx  += __shfl_xor_sync(0xffffffffu, dx, o);
    }
    if (lane == 0) { g_tn2[w] = tn2; g_score[w] = tn2 - 2.f * dx; }
}

// ---------------- stage A: warp-per-chunk register top-20, no syncs ----------------
__global__ void k_topk_a(int src, int n, int nch) {
    int wg   = blockIdx.x * (blockDim.x >> 5) + (threadIdx.x >> 5);
    int lane = threadIdx.x & 31;
    int rows = src ? KNN : 1;
    if (wg >= rows * nch) return;
    int row = wg / nch, c = wg % nch;
    const float* v = src ? (g_sq + (size_t)row * n) : g_score;
    int base = c * CHUNK;

    float val[32];
#pragma unroll
    for (int r = 0; r < 32; r++) {
        int g = base + lane + 32 * r;
        val[r] = (g < n) ? v[g] : FINF;
    }
    float* od = g_cand_d + ((size_t)row * MAXCH + c) * KNN;
    int*   oi = g_cand_i + ((size_t)row * MAXCH + c) * KNN;
    int ibase = base + lane;

    for (int it = 0; it < KNN; it++) {
        float bv = val[0]; int br = 0;
#pragma unroll
        for (int r = 1; r < 32; r++)
            if (val[r] < bv) { bv = val[r]; br = r; }
        int bi = (bv >= FINF) ? 0x7fffffff : (ibase + (br << 5));
#pragma unroll
        for (int o = 16; o; o >>= 1) {
            float ov = __shfl_xor_sync(0xffffffffu, bv, o);
            int   oj = __shfl_xor_sync(0xffffffffu, bi, o);
            if (ov < bv || (ov == bv && oj < bi)) { bv = ov; bi = oj; }
        }
        int rel = bi - ibase;
#pragma unroll
        for (int r = 0; r < 32; r++)
            if (rel == (r << 5)) val[r] = FINF;
        if (lane == 0) { od[it] = bv; oi[it] = bi; }
    }
}

// ---------------- stage B: 2-phase warp-register merge, fused epilogues ----------------
__global__ void k_topk_b(int nchunks, int mode, const float* __restrict__ X,
                         const float* __restrict__ T, int n) {
    int row = blockIdx.x;
    int m = nchunks * KNN;
    int tid = threadIdx.x, lane = tid & 31, w = tid >> 5;
    __shared__ float s_cv[8 * KNN];
    __shared__ int   s_ci[8 * KNN];
    __shared__ int   s_fi[KNN];
    const float* cd = g_cand_d + (size_t)row * MAXCH * KNN;
    const int*   ci = g_cand_i + (size_t)row * MAXCH * KNN;

    float val[8]; int idx[8];
#pragma unroll
    for (int r = 0; r < 8; r++) {
        int j = w * 256 + lane + 32 * r;
        bool ok = j < m;
        val[r] = ok ? cd[j] : FINF;
        idx[r] = ok ? ci[j] : 0x7fffffff;
    }
    for (int it = 0; it < KNN; it++) {
        float bv = val[0]; int bi = idx[0];
#pragma unroll
        for (int r = 1; r < 8; r++)
            if (val[r] < bv || (val[r] == bv && idx[r] < bi)) { bv = val[r]; bi = idx[r]; }
#pragma unroll
        for (int o = 16; o; o >>= 1) {
            float ov = __shfl_xor_sync(0xffffffffu, bv, o);
            int   oj = __shfl_xor_sync(0xffffffffu, bi, o);
            if (ov < bv || (ov == bv && oj < bi)) { bv = ov; bi = oj; }
        }
#pragma unroll
        for (int r = 0; r < 8; r++)
            if (idx[r] == bi) val[r] = FINF;
        if (lane == 0) { s_cv[w * KNN + it] = bv; s_ci[w * KNN + it] = bi; }
    }
    __syncthreads();

    if (w == 0) {
        float v2[5]; int i2[5];
#pragma unroll
        for (int r = 0; r < 5; r++) { int j = lane + 32 * r; v2[r] = s_cv[j]; i2[r] = s_ci[j]; }
        for (int it = 0; it < KNN; it++) {
            float bv = v2[0]; int bi = i2[0];
#pragma unroll
            for (int r = 1; r < 5; r++)
                if (v2[r] < bv || (v2[r] == bv && i2[r] < bi)) { bv = v2[r]; bi = i2[r]; }
#pragma unroll
            for (int o = 16; o; o >>= 1) {
                float ov = __shfl_xor_sync(0xffffffffu, bv, o);
                int   oj = __shfl_xor_sync(0xffffffffu, bi, o);
                if (ov < bv || (ov == bv && oj < bi)) { bv = ov; bi = oj; }
            }
#pragma unroll
            for (int r = 0; r < 5; r++)
                if (i2[r] == bi) v2[r] = FINF;
            if (lane == 0) s_fi[it] = bi;
        }
    }
    __syncthreads();

    if (mode == 0) {
        for (int i = w; i < KNN; i += 8) {
            int rowi = s_fi[i];
            float px = 0.f;
#pragma unroll
            for (int q = 0; q < 4; q++) {
                float4 t = ((const float4*)(T + (size_t)rowi * D))[lane + 32 * q];
                float4 x = ((const float4*)X)[lane + 32 * q];
                ((float4*)g_nb)[i * (D / 4) + lane + 32 * q] = t;
                float a = t.x - x.x, b = t.y - x.y, cc = t.z - x.z, d = t.w - x.w;
                px += a * a + b * b + cc * cc + d * d;
            }
#pragma unroll
            for (int o = 16; o; o >>= 1) px += __shfl_xor_sync(0xffffffffu, px, o);
            if (lane == 0) g_pxk[i] = px;
        }
    } else {
        for (int j = w; j < KNN; j += 8) {
            int rowj = s_fi[j];
            float s = 0.f;
#pragma unroll
            for (int q = 0; q < 4; q++) {
                float4 t  = ((const float4*)(T + (size_t)rowj * D))[lane + 32 * q];
                float4 nb = ((const float4*)g_nb)[row * (D / 4) + lane + 32 * q];
                float a = t.x - nb.x, b = t.y - nb.y, cc = t.z - nb.z, d = t.w - nb.w;
                s += a * a + b * b + cc * cc + d * d;
            }
#pragma unroll
            for (int o = 16; o; o >>= 1) s += __shfl_xor_sync(0xffffffffu, s, o);
            if (lane == 0) g_sqnn[row * KNN + j] = s;
        }
    }
}

// ---- pass 2: k-split warp pairs. Pair = 2 warps x 64 points; warp does 10 k's. ----
#define P2T   256                 // 8 warps = 4 pairs
#define PPTS  64                  // points per pair (2 per lane: lane, lane+32)
#define P2P   256                 // points per block
#define KH    10                  // k's per warp
#define DCF   16                  // floats per chunk per point
#define NCH2  (D / DCF)           // 32 chunks
#define ROWB  80                  // bytes per point row per stage (64 + 16 pad, conflict-free)
#define TSTG  (PPTS * ROWB)       // 5120 B per stage
#define NBSZ  (KNN * D * 4)       // 40960 B resident nb tile
#define SMEM2 (NBSZ + 4 * 2 * TSTG)   // 81920 B

static __device__ __forceinline__ void cpa16(unsigned int dst, const float* src, int sz) {
    asm volatile("cp.async.cg.shared.global [%0], [%1], 16, %2;"
                 :: "r"(dst), "l"(src), "r"(sz));
}

// each warp of the pair fills its 32-point half of the pair's stage buffer
static __device__ __forceinline__ void p2_issue(const float* __restrict__ T, int n,
                                                int ppbase, int lane, int kh,
                                                unsigned int tb, int c) {
#pragma unroll
    for (int rr = 0; rr < 4; rr++) {
        int q  = lane + rr * 32;            // 128 granules = 32 pts x 4
        int pt = kh * 32 + (q >> 2), fc = q & 3;
        int gp = ppbase + pt;
        int sz = (gp < n) ? 16 : 0;
        const float* src = T + (size_t)(gp < n ? gp : 0) * D + c * DCF + fc * 4;
        cpa16(tb + pt * ROWB + fc * 16, src, sz);
    }
    asm volatile("cp.async.commit_group;");
}

__global__ __launch_bounds__(P2T, 2) void k_pass2(const float* __restrict__ T, int n) {
    extern __shared__ char sh[];
    int tid  = threadIdx.x;
    int lane = tid & 31, w = tid >> 5;
    int pair = w >> 1, kh = w & 1;          // kh=0: k 0..9, kh=1: k 10..19
    int koff = kh * KH;
    int barid = pair + 1;                   // named barriers 1..4
    int ppbase = blockIdx.x * P2P + pair * PPTS;

    char* pstage = sh + NBSZ + pair * 2 * TSTG;
    unsigned int pb = (unsigned int)__cvta_generic_to_shared(pstage);

    // kick off chunks 0,1 (each warp loads its half; one group per chunk)
    p2_issue(T, n, ppbase, lane, kh, pb, 0);
    p2_issue(T, n, ppbase, lane, kh, pb + TSTG, 1);

    // resident nb tile (whole block cooperates)
    {
        const unsigned long long* nbsrc = (const unsigned long long*)g_nb;
        unsigned long long* nbdst = (unsigned long long*)sh;
        for (int i = tid; i < KNN * (D / 2); i += P2T) nbdst[i] = nbsrc[i];
    }
    __syncthreads();

    const ulonglong2* s_nb = (const ulonglong2*)sh;   // [KNN][D/4] u128

    unsigned long long a0[KH], a1[KH];
#pragma unroll
    for (int k = 0; k < KH; k++) { a0[k] = 0ull; a1[k] = 0ull; }

#pragma unroll 1
    for (int c = 0; c < NCH2; c++) {
        if (c == NCH2 - 1) asm volatile("cp.async.wait_group 0;");
        else               asm volatile("cp.async.wait_group 1;");
        asm volatile("bar.sync %0, 64;" :: "r"(barid) : "memory");  // t[c] pair-visible

        const char* stage = pstage + (c & 1) * TSTG;
        const ulonglong2* t0p = (const ulonglong2*)(stage + lane * ROWB);
        const ulonglong2* t1p = (const ulonglong2*)(stage + (lane + 32) * ROWB);
        const ulonglong2* nbc = s_nb + c * 4;
#pragma unroll
        for (int dq = 0; dq < DCF / 4; dq++) {
            ulonglong2 t0 = t0p[dq];
            ulonglong2 t1 = t1p[dq];
#pragma unroll
            for (int k = 0; k < KH; k++) {
                ulonglong2 nb = nbc[(koff + k) * (D / 4) + dq];
                fma2(a0[k], t0.x, nb.x);
                fma2(a0[k], t0.y, nb.y);
                fma2(a1[k], t1.x, nb.x);
                fma2(a1[k], t1.y, nb.y);
            }
        }
        asm volatile("bar.sync %0, 64;" :: "r"(barid) : "memory");  // done with t[c]
        if (c + 2 < NCH2)
            p2_issue(T, n, ppbase, lane, kh, pb + (c & 1) * TSTG, c + 2);
    }

    int g0 = ppbase + lane, g1 = ppbase + lane + 32;
    bool v0 = g0 < n, v1 = g1 < n;
    float tn0 = v0 ? g_tn2[g0] : 0.f;
    float tn1 = v1 ? g_tn2[g1] : 0.f;
#pragma unroll
    for (int k = 0; k < KH; k++) {
        float2 f0 = u2f(a0[k]);
        float2 f1 = u2f(a1[k]);
        if (v0) g_sq[(size_t)(koff + k) * n + g0] = tn0 - 2.f * (f0.x + f0.y);
        if (v1) g_sq[(size_t)(koff + k) * n + g1] = tn1 - 2.f * (f1.x + f1.y);
    }
}

// ---------------- final scalar ----------------
__global__ void k_final(float* out) {
    int lane = threadIdx.x;
    float norm = 0.f, px = 0.f;
    if (lane < KNN) {
        float s = 0.f;
#pragma unroll
        for (int j = 0; j < KNN; j++) s += g_sqnn[lane * KNN + j];
        norm = sqrtf(s / (float)KNN);
        px = g_pxk[lane];
    }
#pragma unroll
    for (int o = 16; o; o >>= 1) {
        norm += __shfl_xor_sync(0xffffffffu, norm, o);
        px   += __shfl_xor_sync(0xffffffffu, px, o);
    }
    if (lane == 0) {
        float pdx = sqrtf(px / (float)KNN);
        float lof = pdx / norm * (float)KNN - 1.f;
        float r = erff(lof * 0.7071067811865476f);
        out[0] = fmaxf(r, 0.f);
    }
}

// ---------------- launch ----------------
extern "C" void kernel_launch(void* const* d_in, const int* in_sizes, int n_in,
                              void* d_out, int out_size) {
    const float* A = (const float*)d_in[0];
    const float* B = (const float*)d_in[1];
    const float *X, *T;
    int n;
    if (in_sizes[0] == D) { X = A; T = B; n = in_sizes[1] / D; }
    else                  { X = B; T = A; n = in_sizes[0] / D; }
    if (n > MAXN) n = MAXN;

    int nch = (n + CHUNK - 1) / CHUNK;

    cudaFuncSetAttribute(k_pass2, cudaFuncAttributeMaxDynamicSharedMemorySize, SMEM2);

    k_pass1<<<(n + 7) / 8, 256>>>(X, T, n);
    k_topk_a<<<(nch + 7) / 8, 256>>>(0, n, nch);
    k_topk_b<<<1, 256>>>(nch, 0, X, T, n);
    k_pass2<<<(n + P2P - 1) / P2P, P2T, SMEM2>>>(T, n);
    k_topk_a<<<(nch * KNN + 7) / 8, 256>>>(1, n, nch);
    k_topk_b<<<KNN, 256>>>(nch, 1, X, T, n);
    k_final<<<1, 32>>>((float*)d_out);
}

// round 11
// speedup vs baseline: 1.2398x; 1.1493x over previous
#include <cuda_runtime.h>
#include <cuda_bf16.h>
#include <math.h>

#define D      512
#define KNN    20
#define MAXN   100000
#define MAXCH  128
#define CHUNK  1024
#define FINF   3.0e38f

// ---------------- persistent scratch ----------------
__device__ float g_tn2[MAXN];
__device__ float g_score[MAXN];
__device__ float g_sq[KNN * MAXN];
__device__ float g_cand_d[KNN * MAXCH * KNN];
__device__ int   g_cand_i[KNN * MAXCH * KNN];
__device__ float g_nb[KNN * D];
__device__ float g_pxk[KNN];
__device__ float g_sqnn[KNN * KNN];
__device__ unsigned g_nbh[32 * (D / 2)];   // bf16x2 neighbors, rows 20..31 zero

// pack two f32 into bf16x2 (lo = first arg)
#define CVTB(res, lo, hi) \
    asm("cvt.rn.bf16x2.f32 %0, %1, %2;" : "=r"(res) : "f"(hi), "f"(lo))

// ---------------- pass 1: tn2 and score = tn2 - 2*dot(X,t) ----------------
__global__ void k_pass1(const float* __restrict__ X, const float* __restrict__ T, int n) {
    int w    = blockIdx.x * (blockDim.x >> 5) + (threadIdx.x >> 5);
    int lane = threadIdx.x & 31;
    if (w >= n) return;
    const float4* row = (const float4*)(T + (size_t)w * D);
    const float4* xv  = (const float4*)X;
    float tn2 = 0.f, dx = 0.f;
#pragma unroll
    for (int i = 0; i < 4; i++) {
        float4 t = row[lane + 32 * i];
        float4 x = __ldg(&xv[lane + 32 * i]);
        tn2 += t.x * t.x + t.y * t.y + t.z * t.z + t.w * t.w;
        dx  += t.x * x.x + t.y * x.y + t.z * x.z + t.w * x.w;
    }
#pragma unroll
    for (int o = 16; o; o >>= 1) {
        tn2 += __shfl_xor_sync(0xffffffffu, tn2, o);
        dx  += __shfl_xor_sync(0xffffffffu, dx, o);
    }
    if (lane == 0) { g_tn2[w] = tn2; g_score[w] = tn2 - 2.f * dx; }
}

// ---------------- stage A: warp-per-chunk register top-20 ----------------
__global__ void k_topk_a(int src, int n, int nch) {
    int wg   = blockIdx.x * (blockDim.x >> 5) + (threadIdx.x >> 5);
    int lane = threadIdx.x & 31;
    int rows = src ? KNN : 1;
    if (wg >= rows * nch) return;
    int row = wg / nch, c = wg % nch;
    const float* v = src ? (g_sq + (size_t)row * n) : g_score;
    int base = c * CHUNK;

    float val[32];
#pragma unroll
    for (int r = 0; r < 32; r++) {
        int g = base + lane + 32 * r;
        val[r] = (g < n) ? v[g] : FINF;
    }
    float* od = g_cand_d + ((size_t)row * MAXCH + c) * KNN;
    int*   oi = g_cand_i + ((size_t)row * MAXCH + c) * KNN;
    int ibase = base + lane;

    for (int it = 0; it < KNN; it++) {
        float bv = val[0]; int br = 0;
#pragma unroll
        for (int r = 1; r < 32; r++)
            if (val[r] < bv) { bv = val[r]; br = r; }
        int bi = (bv >= FINF) ? 0x7fffffff : (ibase + (br << 5));
#pragma unroll
        for (int o = 16; o; o >>= 1) {
            float ov = __shfl_xor_sync(0xffffffffu, bv, o);
            int   oj = __shfl_xor_sync(0xffffffffu, bi, o);
            if (ov < bv || (ov == bv && oj < bi)) { bv = ov; bi = oj; }
        }
        int rel = bi - ibase;
#pragma unroll
        for (int r = 0; r < 32; r++)
            if (rel == (r << 5)) val[r] = FINF;
        if (lane == 0) { od[it] = bv; oi[it] = bi; }
    }
}

// ---------------- stage B: merge + fused epilogues ----------------
__global__ void k_topk_b(int nchunks, int mode, const float* __restrict__ X,
                         const float* __restrict__ T, int n) {
    int row = blockIdx.x;
    int m = nchunks * KNN;
    int tid = threadIdx.x, lane = tid & 31, w = tid >> 5;
    __shared__ float s_cv[8 * KNN];
    __shared__ int   s_ci[8 * KNN];
    __shared__ int   s_fi[KNN];
    const float* cd = g_cand_d + (size_t)row * MAXCH * KNN;
    const int*   ci = g_cand_i + (size_t)row * MAXCH * KNN;

    float val[8]; int idx[8];
#pragma unroll
    for (int r = 0; r < 8; r++) {
        int j = w * 256 + lane + 32 * r;
        bool ok = j < m;
        val[r] = ok ? cd[j] : FINF;
        idx[r] = ok ? ci[j] : 0x7fffffff;
    }
    for (int it = 0; it < KNN; it++) {
        float bv = val[0]; int bi = idx[0];
#pragma unroll
        for (int r = 1; r < 8; r++)
            if (val[r] < bv || (val[r] == bv && idx[r] < bi)) { bv = val[r]; bi = idx[r]; }
#pragma unroll
        for (int o = 16; o; o >>= 1) {
            float ov = __shfl_xor_sync(0xffffffffu, bv, o);
            int   oj = __shfl_xor_sync(0xffffffffu, bi, o);
            if (ov < bv || (ov == bv && oj < bi)) { bv = ov; bi = oj; }
        }
#pragma unroll
        for (int r = 0; r < 8; r++)
            if (idx[r] == bi) val[r] = FINF;
        if (lane == 0) { s_cv[w * KNN + it] = bv; s_ci[w * KNN + it] = bi; }
    }
    __syncthreads();

    if (w == 0) {
        float v2[5]; int i2[5];
#pragma unroll
        for (int r = 0; r < 5; r++) { int j = lane + 32 * r; v2[r] = s_cv[j]; i2[r] = s_ci[j]; }
        for (int it = 0; it < KNN; it++) {
            float bv = v2[0]; int bi = i2[0];
#pragma unroll
            for (int r = 1; r < 5; r++)
                if (v2[r] < bv || (v2[r] == bv && i2[r] < bi)) { bv = v2[r]; bi = i2[r]; }
#pragma unroll
            for (int o = 16; o; o >>= 1) {
                float ov = __shfl_xor_sync(0xffffffffu, bv, o);
                int   oj = __shfl_xor_sync(0xffffffffu, bi, o);
                if (ov < bv || (ov == bv && oj < bi)) { bv = ov; bi = oj; }
            }
#pragma unroll
            for (int r = 0; r < 5; r++)
                if (i2[r] == bi) v2[r] = FINF;
            if (lane == 0) s_fi[it] = bi;
        }
    }
    __syncthreads();

    if (mode == 0) {
        // fused gather: fp32 copy + exact ||nb-X||^2 + bf16 copy for the MMA B operand
        for (int i = w; i < KNN; i += 8) {
            int rowi = s_fi[i];
            float px = 0.f;
#pragma unroll
            for (int q = 0; q < 4; q++) {
                float4 t = ((const float4*)(T + (size_t)rowi * D))[lane + 32 * q];
                float4 x = ((const float4*)X)[lane + 32 * q];
                ((float4*)g_nb)[i * (D / 4) + lane + 32 * q] = t;
                unsigned blo, bhi;
                CVTB(blo, t.x, t.y);
                CVTB(bhi, t.z, t.w);
                uint2 u; u.x = blo; u.y = bhi;
                *(uint2*)&g_nbh[i * (D / 2) + q * 64 + 2 * lane] = u;
                float a = t.x - x.x, b = t.y - x.y, cc = t.z - x.z, d = t.w - x.w;
                px += a * a + b * b + cc * cc + d * d;
            }
#pragma unroll
            for (int o = 16; o; o >>= 1) px += __shfl_xor_sync(0xffffffffu, px, o);
            if (lane == 0) g_pxk[i] = px;
        }
        // zero pad rows 20..31 of g_nbh
        for (int i = KNN + w; i < 32; i += 8)
            for (int q = lane; q < D / 2; q += 32) g_nbh[i * (D / 2) + q] = 0u;
    } else {
        for (int j = w; j < KNN; j += 8) {
            int rowj = s_fi[j];
            float s = 0.f;
#pragma unroll
            for (int q = 0; q < 4; q++) {
                float4 t  = ((const float4*)(T + (size_t)rowj * D))[lane + 32 * q];
                float4 nb = ((const float4*)g_nb)[row * (D / 4) + lane + 32 * q];
                float a = t.x - nb.x, b = t.y - nb.y, cc = t.z - nb.z, d = t.w - nb.w;
                s += a * a + b * b + cc * cc + d * d;
            }
#pragma unroll
            for (int o = 16; o; o >>= 1) s += __shfl_xor_sync(0xffffffffu, s, o);
            if (lane == 0) g_sqnn[row * KNN + j] = s;
        }
    }
}

// ---------------- pass 2: warp-tile HMMA GEMM (mma.sync m16n8k16 bf16) ----------------
// warp computes D[32 pts x 32 cols] = A[32 x 512] * B[32 x 512]^T; 20 cols real.
static __device__ __forceinline__ void mma16816(float* c, const unsigned* a, const unsigned* b) {
    asm volatile(
        "mma.sync.aligned.m16n8k16.row.col.f32.bf16.bf16.f32 "
        "{%0,%1,%2,%3}, {%4,%5,%6,%7}, {%8,%9}, {%0,%1,%2,%3};"
        : "+f"(c[0]), "+f"(c[1]), "+f"(c[2]), "+f"(c[3])
        : "r"(a[0]), "r"(a[1]), "r"(a[2]), "r"(a[3]), "r"(b[0]), "r"(b[1]));
}

__global__ __launch_bounds__(128) void k_pass2(const float* __restrict__ T, int n) {
    int tid = threadIdx.x, lane = tid & 31, w = tid >> 5;
    int qr = lane >> 2, qc = lane & 3;            // fragment row / col-pair
    int pbase = blockIdx.x * 128 + w * 32;

    // A row pointers (as float2), rows clamped for the tail tile
    const float2* rA[4];
#pragma unroll
    for (int j = 0; j < 4; j++) {
        int mt = j >> 1;
        int r = pbase + mt * 16 + qr + (j & 1) * 8;
        if (r >= n) r = n - 1;
        rA[j] = (const float2*)(T + (size_t)r * D);
    }
    const unsigned* Bq[4];
#pragma unroll
    for (int nt = 0; nt < 4; nt++) Bq[nt] = g_nbh + (nt * 8 + qr) * (D / 2);

    float acc[2][4][4];
#pragma unroll
    for (int mt = 0; mt < 2; mt++)
#pragma unroll
        for (int nt = 0; nt < 4; nt++)
#pragma unroll
            for (int q = 0; q < 4; q++) acc[mt][nt][q] = 0.f;

#pragma unroll 4
    for (int c = 0; c < 32; c++) {
        int kb = c * 8 + qc;                      // float2 / bf16x2 index
        unsigned b[4][2];
#pragma unroll
        for (int nt = 0; nt < 4; nt++) {
            b[nt][0] = __ldg(Bq[nt] + kb);
            b[nt][1] = __ldg(Bq[nt] + kb + 4);
        }
        unsigned a[2][4];
#pragma unroll
        for (int mt = 0; mt < 2; mt++) {
            float2 f00 = __ldg(rA[2 * mt] + kb);
            float2 f10 = __ldg(rA[2 * mt + 1] + kb);
            float2 f01 = __ldg(rA[2 * mt] + kb + 4);
            float2 f11 = __ldg(rA[2 * mt + 1] + kb + 4);
            CVTB(a[mt][0], f00.x, f00.y);
            CVTB(a[mt][1], f10.x, f10.y);
            CVTB(a[mt][2], f01.x, f01.y);
            CVTB(a[mt][3], f11.x, f11.y);
        }
#pragma unroll
        for (int mt = 0; mt < 2; mt++)
#pragma unroll
            for (int nt = 0; nt < 4; nt++)
                mma16816(acc[mt][nt], a[mt], b[nt]);
    }

    // epilogue: g_sq[k][p] = tn2[p] - 2*dot
#pragma unroll
    for (int mt = 0; mt < 2; mt++) {
        int p0 = pbase + mt * 16 + qr;
        int p1 = p0 + 8;
        float tn0 = (p0 < n) ? g_tn2[p0] : 0.f;
        float tn1 = (p1 < n) ? g_tn2[p1] : 0.f;
#pragma unroll
        for (int nt = 0; nt < 4; nt++) {
            int k0 = nt * 8 + qc * 2;
            if (k0 < KNN) {
                if (p0 < n) g_sq[(size_t)k0 * n + p0] = tn0 - 2.f * acc[mt][nt][0];
                if (p1 < n) g_sq[(size_t)k0 * n + p1] = tn1 - 2.f * acc[mt][nt][2];
            }
            if (k0 + 1 < KNN) {
                if (p0 < n) g_sq[(size_t)(k0 + 1) * n + p0] = tn0 - 2.f * acc[mt][nt][1];
                if (p1 < n) g_sq[(size_t)(k0 + 1) * n + p1] = tn1 - 2.f * acc[mt][nt][3];
            }
        }
    }
}

// ---------------- final scalar ----------------
__global__ void k_final(float* out) {
    int lane = threadIdx.x;
    float norm = 0.f, px = 0.f;
    if (lane < KNN) {
        float s = 0.f;
#pragma unroll
        for (int j = 0; j < KNN; j++) s += g_sqnn[lane * KNN + j];
        norm = sqrtf(s / (float)KNN);
        px = g_pxk[lane];
    }
#pragma unroll
    for (int o = 16; o; o >>= 1) {
        norm += __shfl_xor_sync(0xffffffffu, norm, o);
        px   += __shfl_xor_sync(0xffffffffu, px, o);
    }
    if (lane == 0) {
        float pdx = sqrtf(px / (float)KNN);
        float lof = pdx / norm * (float)KNN - 1.f;
        float r = erff(lof * 0.7071067811865476f);
        out[0] = fmaxf(r, 0.f);
    }
}

// ---------------- launch ----------------
extern "C" void kernel_launch(void* const* d_in, const int* in_sizes, int n_in,
                              void* d_out, int out_size) {
    const float* A = (const float*)d_in[0];
    const float* B = (const float*)d_in[1];
    const float *X, *T;
    int n;
    if (in_sizes[0] == D) { X = A; T = B; n = in_sizes[1] / D; }
    else                  { X = B; T = A; n = in_sizes[0] / D; }
    if (n > MAXN) n = MAXN;

    int nch = (n + CHUNK - 1) / CHUNK;

    k_pass1<<<(n + 7) / 8, 256>>>(X, T, n);
    k_topk_a<<<(nch + 7) / 8, 256>>>(0, n, nch);
    k_topk_b<<<1, 256>>>(nch, 0, X, T, n);
    k_pass2<<<(n + 127) / 128, 128>>>(T, n);
    k_topk_a<<<(nch * KNN + 7) / 8, 256>>>(1, n, nch);
    k_topk_b<<<KNN, 256>>>(nch, 1, X, T, n);
    k_final<<<1, 32>>>((float*)d_out);
}

// round 12
// speedup vs baseline: 1.3383x; 1.0795x over previous
#include <cuda_runtime.h>
#include <cuda_bf16.h>
#include <math.h>

#define D      512
#define KNN    20
#define MAXN   100000
#define MAXCH  128
#define CHUNK  1024
#define FINF   3.0e38f

// ---------------- persistent scratch ----------------
__device__ float g_tn2[MAXN];
__device__ float g_score[MAXN];
__device__ float g_sq[KNN * MAXN];
__device__ float g_cand_d[KNN * MAXCH * KNN];
__device__ int   g_cand_i[KNN * MAXCH * KNN];
__device__ float g_nb[KNN * D];
__device__ float g_pxk[KNN];
__device__ float g_sqnn[KNN * KNN];
__device__ unsigned g_nbh[32 * (D / 2)];   // bf16x2 neighbors, rows 20..31 zero

// pack two f32 into bf16x2 (lo = first arg)
#define CVTB(res, lo, hi) \
    asm("cvt.rn.bf16x2.f32 %0, %1, %2;" : "=r"(res) : "f"(hi), "f"(lo))

// ---------------- pass 1: tn2 and score = tn2 - 2*dot(X,t) ----------------
__global__ void k_pass1(const float* __restrict__ X, const float* __restrict__ T, int n) {
    int w    = blockIdx.x * (blockDim.x >> 5) + (threadIdx.x >> 5);
    int lane = threadIdx.x & 31;
    if (w >= n) return;
    const float4* row = (const float4*)(T + (size_t)w * D);
    const float4* xv  = (const float4*)X;
    float tn2 = 0.f, dx = 0.f;
#pragma unroll
    for (int i = 0; i < 4; i++) {
        float4 t = row[lane + 32 * i];
        float4 x = __ldg(&xv[lane + 32 * i]);
        tn2 += t.x * t.x + t.y * t.y + t.z * t.z + t.w * t.w;
        dx  += t.x * x.x + t.y * x.y + t.z * x.z + t.w * x.w;
    }
#pragma unroll
    for (int o = 16; o; o >>= 1) {
        tn2 += __shfl_xor_sync(0xffffffffu, tn2, o);
        dx  += __shfl_xor_sync(0xffffffffu, dx, o);
    }
    if (lane == 0) { g_tn2[w] = tn2; g_score[w] = tn2 - 2.f * dx; }
}

// ---------------- stage A: warp-per-chunk register top-20 ----------------
__global__ void k_topk_a(int src, int n, int nch) {
    int wg   = blockIdx.x * (blockDim.x >> 5) + (threadIdx.x >> 5);
    int lane = threadIdx.x & 31;
    int rows = src ? KNN : 1;
    if (wg >= rows * nch) return;
    int row = wg / nch, c = wg % nch;
    const float* v = src ? (g_sq + (size_t)row * n) : g_score;
    int base = c * CHUNK;

    float val[32];
#pragma unroll
    for (int r = 0; r < 32; r++) {
        int g = base + lane + 32 * r;
        val[r] = (g < n) ? v[g] : FINF;
    }
    float* od = g_cand_d + ((size_t)row * MAXCH + c) * KNN;
    int*   oi = g_cand_i + ((size_t)row * MAXCH + c) * KNN;
    int ibase = base + lane;

    for (int it = 0; it < KNN; it++) {
        float bv = val[0]; int br = 0;
#pragma unroll
        for (int r = 1; r < 32; r++)
            if (val[r] < bv) { bv = val[r]; br = r; }
        int bi = (bv >= FINF) ? 0x7fffffff : (ibase + (br << 5));
#pragma unroll
        for (int o = 16; o; o >>= 1) {
            float ov = __shfl_xor_sync(0xffffffffu, bv, o);
            int   oj = __shfl_xor_sync(0xffffffffu, bi, o);
            if (ov < bv || (ov == bv && oj < bi)) { bv = ov; bi = oj; }
        }
        int rel = bi - ibase;
#pragma unroll
        for (int r = 0; r < 32; r++)
            if (rel == (r << 5)) val[r] = FINF;
        if (lane == 0) { od[it] = bv; oi[it] = bi; }
    }
}

// ---------------- stage B: merge + fused epilogues ----------------
__global__ void k_topk_b(int nchunks, int mode, const float* __restrict__ X,
                         const float* __restrict__ T, int n) {
    int row = blockIdx.x;
    int m = nchunks * KNN;
    int tid = threadIdx.x, lane = tid & 31, w = tid >> 5;
    __shared__ float s_cv[8 * KNN];
    __shared__ int   s_ci[8 * KNN];
    __shared__ int   s_fi[KNN];
    const float* cd = g_cand_d + (size_t)row * MAXCH * KNN;
    const int*   ci = g_cand_i + (size_t)row * MAXCH * KNN;

    float val[8]; int idx[8];
#pragma unroll
    for (int r = 0; r < 8; r++) {
        int j = w * 256 + lane + 32 * r;
        bool ok = j < m;
        val[r] = ok ? cd[j] : FINF;
        idx[r] = ok ? ci[j] : 0x7fffffff;
    }
    for (int it = 0; it < KNN; it++) {
        float bv = val[0]; int bi = idx[0];
#pragma unroll
        for (int r = 1; r < 8; r++)
            if (val[r] < bv || (val[r] == bv && idx[r] < bi)) { bv = val[r]; bi = idx[r]; }
#pragma unroll
        for (int o = 16; o; o >>= 1) {
            float ov = __shfl_xor_sync(0xffffffffu, bv, o);
            int   oj = __shfl_xor_sync(0xffffffffu, bi, o);
            if (ov < bv || (ov == bv && oj < bi)) { bv = ov; bi = oj; }
        }
#pragma unroll
        for (int r = 0; r < 8; r++)
            if (idx[r] == bi) val[r] = FINF;
        if (lane == 0) { s_cv[w * KNN + it] = bv; s_ci[w * KNN + it] = bi; }
    }
    __syncthreads();

    if (w == 0) {
        float v2[5]; int i2[5];
#pragma unroll
        for (int r = 0; r < 5; r++) { int j = lane + 32 * r; v2[r] = s_cv[j]; i2[r] = s_ci[j]; }
        for (int it = 0; it < KNN; it++) {
            float bv = v2[0]; int bi = i2[0];
#pragma unroll
            for (int r = 1; r < 5; r++)
                if (v2[r] < bv || (v2[r] == bv && i2[r] < bi)) { bv = v2[r]; bi = i2[r]; }
#pragma unroll
            for (int o = 16; o; o >>= 1) {
                float ov = __shfl_xor_sync(0xffffffffu, bv, o);
                int   oj = __shfl_xor_sync(0xffffffffu, bi, o);
                if (ov < bv || (ov == bv && oj < bi)) { bv = ov; bi = oj; }
            }
#pragma unroll
            for (int r = 0; r < 5; r++)
                if (i2[r] == bi) v2[r] = FINF;
            if (lane == 0) s_fi[it] = bi;
        }
    }
    __syncthreads();

    if (mode == 0) {
        // fused gather: fp32 copy + exact ||nb-X||^2 + bf16 copy for the MMA B operand
        for (int i = w; i < KNN; i += 8) {
            int rowi = s_fi[i];
            float px = 0.f;
#pragma unroll
            for (int q = 0; q < 4; q++) {
                float4 t = ((const float4*)(T + (size_t)rowi * D))[lane + 32 * q];
                float4 x = ((const float4*)X)[lane + 32 * q];
                ((float4*)g_nb)[i * (D / 4) + lane + 32 * q] = t;
                unsigned blo, bhi;
                CVTB(blo, t.x, t.y);
                CVTB(bhi, t.z, t.w);
                uint2 u; u.x = blo; u.y = bhi;
                *(uint2*)&g_nbh[i * (D / 2) + q * 64 + 2 * lane] = u;
                float a = t.x - x.x, b = t.y - x.y, cc = t.z - x.z, d = t.w - x.w;
                px += a * a + b * b + cc * cc + d * d;
            }
#pragma unroll
            for (int o = 16; o; o >>= 1) px += __shfl_xor_sync(0xffffffffu, px, o);
            if (lane == 0) g_pxk[i] = px;
        }
        // zero pad rows 20..31 of g_nbh
        for (int i = KNN + w; i < 32; i += 8)
            for (int q = lane; q < D / 2; q += 32) g_nbh[i * (D / 2) + q] = 0u;
    } else {
        for (int j = w; j < KNN; j += 8) {
            int rowj = s_fi[j];
            float s = 0.f;
#pragma unroll
            for (int q = 0; q < 4; q++) {
                float4 t  = ((const float4*)(T + (size_t)rowj * D))[lane + 32 * q];
                float4 nb = ((const float4*)g_nb)[row * (D / 4) + lane + 32 * q];
                float a = t.x - nb.x, b = t.y - nb.y, cc = t.z - nb.z, d = t.w - nb.w;
                s += a * a + b * b + cc * cc + d * d;
            }
#pragma unroll
            for (int o = 16; o; o >>= 1) s += __shfl_xor_sync(0xffffffffu, s, o);
            if (lane == 0) g_sqnn[row * KNN + j] = s;
        }
    }
}

// ---------------- pass 2: smem + ldmatrix HMMA GEMM ----------------
// block = 128 thr / 4 warps, tile M=128, N=32 (20 real), K=512 in 8 chunks of 64.
// smem: A bf16 double-buffer 2x16KB (swizzled) + B bf16 32KB (swizzled) = 64KB.
#define SA_BYTES 16384
#define SB_OFF   32768
#define SMEM_P2  65536

static __device__ __forceinline__ void mma16816(float* c, const unsigned* a, const unsigned* b) {
    asm volatile(
        "mma.sync.aligned.m16n8k16.row.col.f32.bf16.bf16.f32 "
        "{%0,%1,%2,%3}, {%4,%5,%6,%7}, {%8,%9}, {%0,%1,%2,%3};"
        : "+f"(c[0]), "+f"(c[1]), "+f"(c[2]), "+f"(c[3])
        : "r"(a[0]), "r"(a[1]), "r"(a[2]), "r"(a[3]), "r"(b[0]), "r"(b[1]));
}
static __device__ __forceinline__ void ldsm4(unsigned* r, unsigned addr) {
    asm volatile("ldmatrix.sync.aligned.m8n8.x4.shared.b16 {%0,%1,%2,%3}, [%4];"
                 : "=r"(r[0]), "=r"(r[1]), "=r"(r[2]), "=r"(r[3]) : "r"(addr));
}

__global__ __launch_bounds__(128) void k_pass2(const float* __restrict__ T, int n) {
    extern __shared__ char sh[];
    unsigned sb = (unsigned)__cvta_generic_to_shared(sh);
    int tid = threadIdx.x, lane = tid & 31, w = tid >> 5;
    int qr = lane >> 2, qc = lane & 3;
    int pbase = blockIdx.x * 128;
    int j8 = lane >> 3, r8 = lane & 7;     // ldmatrix address group / row

    // ---- load B (32x512 bf16) into smem, swizzled: addr = n*1024 + ((q ^ (n&7))<<4)
#pragma unroll
    for (int i = 0; i < 16; i++) {
        int lin = tid + i * 128;           // 2048 chunks of 16B
        int nr = lin >> 6, q = lin & 63;
        uint4 v = *(const uint4*)&g_nbh[nr * 256 + q * 4];
        *(uint4*)(sh + SB_OFF + nr * 1024 + ((q ^ (nr & 7)) << 4)) = v;
    }

    // ---- A fp32 prefetch for chunk c into regs (16 LDG.128 = 64 floats)
    float4 r[16];
#define LDG_A(c)                                                                   \
    {                                                                              \
        _Pragma("unroll")                                                          \
        for (int i = 0; i < 8; i++) {                                              \
            int lc = tid + i * 128;                                                \
            int m = lc >> 3, q = lc & 7;                                           \
            int gp = pbase + m; if (gp >= n) gp = n - 1;                           \
            const float4* s4 = (const float4*)(T + (size_t)gp * D + (c) * 64 + q * 8); \
            r[2 * i]     = __ldg(s4);                                              \
            r[2 * i + 1] = __ldg(s4 + 1);                                          \
        }                                                                          \
    }
    // cvt + swizzled STS of regs into buffer buf (generic pointer)
#define STS_A(bufp)                                                                \
    {                                                                              \
        _Pragma("unroll")                                                          \
        for (int i = 0; i < 8; i++) {                                              \
            int lc = tid + i * 128;                                                \
            int m = lc >> 3, q = lc & 7;                                           \
            uint4 u;                                                               \
            CVTB(u.x, r[2 * i].x,     r[2 * i].y);                                 \
            CVTB(u.y, r[2 * i].z,     r[2 * i].w);                                 \
            CVTB(u.z, r[2 * i + 1].x, r[2 * i + 1].y);                             \
            CVTB(u.w, r[2 * i + 1].z, r[2 * i + 1].w);                             \
            *(uint4*)((bufp) + m * 128 + ((q ^ (m & 7)) << 4)) = u;                \
        }                                                                          \
    }

    LDG_A(0);
    STS_A(sh);             // buf0
    LDG_A(1);
    __syncthreads();       // B + A0 visible

    float acc[2][4][4];
#pragma unroll
    for (int mt = 0; mt < 2; mt++)
#pragma unroll
        for (int nt = 0; nt < 4; nt++)
#pragma unroll
            for (int q = 0; q < 4; q++) acc[mt][nt][q] = 0.f;

#pragma unroll 1
    for (int c = 0; c < 8; c++) {
        unsigned bufA = sb + (c & 1) * SA_BYTES;
#pragma unroll
        for (int s = 0; s < 4; s++) {
            unsigned af[2][4], bf[2][4];
            // A fragments: rows mbase + (j8&1)*8 + r8, q = s*2 + (j8>>1)
#pragma unroll
            for (int mt = 0; mt < 2; mt++) {
                int m = w * 32 + mt * 16 + ((j8 & 1) << 3) + r8;
                int q = s * 2 + (j8 >> 1);
                ldsm4(af[mt], bufA + m * 128 + ((q ^ (m & 7)) << 4));
            }
            // B fragments: rows np*16 + ((j8>>1)<<3) + r8, q = (c*4+s)*2 + (j8&1)
#pragma unroll
            for (int np = 0; np < 2; np++) {
                int nr = np * 16 + ((j8 >> 1) << 3) + r8;
                int q = (c * 4 + s) * 2 + (j8 & 1);
                ldsm4(bf[np], sb + SB_OFF + nr * 1024 + ((q ^ (nr & 7)) << 4));
            }
#pragma unroll
            for (int mt = 0; mt < 2; mt++)
#pragma unroll
                for (int np = 0; np < 2; np++) {
                    mma16816(acc[mt][2 * np],     af[mt], &bf[np][0]);
                    mma16816(acc[mt][2 * np + 1], af[mt], &bf[np][2]);
                }
        }
        if (c + 1 < 8) STS_A(sh + ((c + 1) & 1) * SA_BYTES);
        if (c + 2 < 8) LDG_A(c + 2);
        __syncthreads();
    }

    // epilogue: g_sq[k][p] = tn2[p] - 2*dot
#pragma unroll
    for (int mt = 0; mt < 2; mt++) {
        int p0 = pbase + w * 32 + mt * 16 + qr;
        int p1 = p0 + 8;
        float tn0 = (p0 < n) ? g_tn2[p0] : 0.f;
        float tn1 = (p1 < n) ? g_tn2[p1] : 0.f;
#pragma unroll
        for (int nt = 0; nt < 4; nt++) {
            int k0 = nt * 8 + qc * 2;
            if (k0 < KNN) {
                if (p0 < n) g_sq[(size_t)k0 * n + p0] = tn0 - 2.f * acc[mt][nt][0];
                if (p1 < n) g_sq[(size_t)k0 * n + p1] = tn1 - 2.f * acc[mt][nt][2];
            }
            if (k0 + 1 < KNN) {
                if (p0 < n) g_sq[(size_t)(k0 + 1) * n + p0] = tn0 - 2.f * acc[mt][nt][1];
                if (p1 < n) g_sq[(size_t)(k0 + 1) * n + p1] = tn1 - 2.f * acc[mt][nt][3];
            }
        }
    }
}

// ---------------- final scalar ----------------
__global__ void k_final(float* out) {
    int lane = threadIdx.x;
    float norm = 0.f, px = 0.f;
    if (lane < KNN) {
        float s = 0.f;
#pragma unroll
        for (int j = 0; j < KNN; j++) s += g_sqnn[lane * KNN + j];
        norm = sqrtf(s / (float)KNN);
        px = g_pxk[lane];
    }
#pragma unroll
    for (int o = 16; o; o >>= 1) {
        norm += __shfl_xor_sync(0xffffffffu, norm, o);
        px   += __shfl_xor_sync(0xffffffffu, px, o);
    }
    if (lane == 0) {
        float pdx = sqrtf(px / (float)KNN);
        float lof = pdx / norm * (float)KNN - 1.f;
        float r = erff(lof * 0.7071067811865476f);
        out[0] = fmaxf(r, 0.f);
    }
}

// ---------------- launch ----------------
extern "C" void kernel_launch(void* const* d_in, const int* in_sizes, int n_in,
                              void* d_out, int out_size) {
    const float* A = (const float*)d_in[0];
    const float* B = (const float*)d_in[1];
    const float *X, *T;
    int n;
    if (in_sizes[0] == D) { X = A; T = B; n = in_sizes[1] / D; }
    else                  { X = B; T = A; n = in_sizes[0] / D; }
    if (n > MAXN) n = MAXN;

    int nch = (n + CHUNK - 1) / CHUNK;

    cudaFuncSetAttribute(k_pass2, cudaFuncAttributeMaxDynamicSharedMemorySize, SMEM_P2);

    k_pass1<<<(n + 7) / 8, 256>>>(X, T, n);
    k_topk_a<<<(nch + 7) / 8, 256>>>(0, n, nch);
    k_topk_b<<<1, 256>>>(nch, 0, X, T, n);
    k_pass2<<<(n + 127) / 128, 128, SMEM_P2>>>(T, n);
    k_topk_a<<<(nch * KNN + 7) / 8, 256>>>(1, n, nch);
    k_topk_b<<<KNN, 256>>>(nch, 1, X, T, n);
    k_final<<<1, 32>>>((float*)d_out);
}